// round 8
// baseline (speedup 1.0000x reference)
#include <cuda_runtime.h>
#include <math_constants.h>

// Problem constants (fixed by the reference)
#define NM   32      // molecules
#define NA   40      // atoms per molecule
#define NSPEC 4
#define FEAT 384     // 4*16 + 10*32
#define RCR  5.2f
#define RCA  3.5f
#define BLK  128

__global__ __launch_bounds__(BLK)
void aev_kernel(const int* __restrict__ elem,
                const float* __restrict__ coords,
                float* __restrict__ out)
{
    const int bid  = blockIdx.x;        // m*NA + i
    const int m    = bid / NA;
    const int i    = bid % NA;
    const int tid  = threadIdx.x;
    const int lane = tid & 31;
    const int w    = tid >> 5;

    // ---- Warp-private smem (no cross-warp sharing, no __syncthreads) ----
    __shared__ float2 s_rdat[2][NA];          // warps 0,1: {d, fcR}
    __shared__ int    s_relem[2][NA];
    __shared__ float  s_adx[2][NA], s_ady[2][NA], s_adz[2][NA];
    __shared__ float  s_ad[2][NA],  s_afc[2][NA];
    __shared__ int    s_aelem[2][NA];
    __shared__ float4 s_pd[2][32];            // warps 2,3: pair records per round
    __shared__ int    s_pid[2][32];

    const float xi = coords[(m*NA + i)*3 + 0];
    const float yi = coords[(m*NA + i)*3 + 1];
    const float zi = coords[(m*NA + i)*3 + 2];
    float* o = out + bid * FEAT;

    if (w < 2) {
        // ================= RADIAL WARPS (0,1): fully self-sufficient ========
        float2* rdat  = s_rdat[w];
        int*    relem = s_relem[w];

        bool in0 = false, in1 = false;
        float d0 = 0.f, f0 = 0.f, d1 = 0.f, f1 = 0.f;
        int   e0 = 0, e1v = 0;
        {   // atom a0 = lane
            const float* cj = coords + (m*NA + lane)*3;
            float dx = cj[0]-xi, dy = cj[1]-yi, dz = cj[2]-zi;
            d0 = sqrtf(dx*dx + dy*dy + dz*dz + 1e-12f);
            f0 = 0.5f * __cosf((CUDART_PI_F / RCR) * d0) + 0.5f;
            e0 = elem[m*NA + lane];
            in0 = (lane != i) && (d0 < RCR);
        }
        if (lane < 8) {   // atom a1 = lane+32
            const int a1 = lane + 32;
            const float* cj = coords + (m*NA + a1)*3;
            float dx = cj[0]-xi, dy = cj[1]-yi, dz = cj[2]-zi;
            d1 = sqrtf(dx*dx + dy*dy + dz*dz + 1e-12f);
            f1 = 0.5f * __cosf((CUDART_PI_F / RCR) * d1) + 0.5f;
            e1v = elem[m*NA + a1];
            in1 = (a1 != i) && (d1 < RCR);
        }
        const unsigned b0 = __ballot_sync(0xFFFFFFFFu, in0);
        const unsigned b1 = __ballot_sync(0xFFFFFFFFu, in1);
        const unsigned lt = (1u << lane) - 1u;
        if (in0) { int p = __popc(b0 & lt);              rdat[p] = make_float2(d0, f0); relem[p] = e0;  }
        if (in1) { int p = __popc(b0) + __popc(b1 & lt); rdat[p] = make_float2(d1, f1); relem[p] = e1v; }
        const int cntR = __popc(b0) + __popc(b1);
        __syncwarp();

        // feature f = w*32 + lane : species s = f>>4, shift fr = f&15
        const int f  = w*32 + lane;
        const int s  = f >> 4;
        const int fr = f & 15;
        const float shf = 0.9f + 0.26875f * (float)fr;
        float acc = 0.0f;
        #pragma unroll 4
        for (int n = 0; n < cntR; n++) {
            float2 rd = rdat[n];
            int    re = relem[n];
            float dd = rd.x - shf;
            float t  = 0.25f * __expf(-16.0f * dd * dd) * rd.y;
            acc += (re == s) ? t : 0.0f;
        }
        o[f] = acc;
    } else {
        // ================= ANGULAR WARPS (2,3): fully self-sufficient =======
        const int  aw   = w - 2;           // 0 or 1
        float* adx = s_adx[aw]; float* ady = s_ady[aw]; float* adz = s_adz[aw];
        float* ad  = s_ad[aw];  float* afc = s_afc[aw];
        int*   ael = s_aelem[aw];
        float4* pd  = s_pd[aw];
        int*    pidb = s_pid[aw];

        bool in0 = false, in1 = false;
        float dx0=0,dy0=0,dz0=0,d0=0,f0=0, dx1=0,dy1=0,dz1=0,d1=0,f1=0;
        int e0 = 0, e1v = 0;
        {   // atom a0 = lane
            const float* cj = coords + (m*NA + lane)*3;
            dx0 = cj[0]-xi; dy0 = cj[1]-yi; dz0 = cj[2]-zi;
            d0 = sqrtf(dx0*dx0 + dy0*dy0 + dz0*dz0 + 1e-12f);
            f0 = 0.5f * __cosf((CUDART_PI_F / RCA) * d0) + 0.5f;
            e0 = elem[m*NA + lane];
            in0 = (lane != i) && (d0 < RCA);
        }
        if (lane < 8) {   // atom a1 = lane+32
            const int a1 = lane + 32;
            const float* cj = coords + (m*NA + a1)*3;
            dx1 = cj[0]-xi; dy1 = cj[1]-yi; dz1 = cj[2]-zi;
            d1 = sqrtf(dx1*dx1 + dy1*dy1 + dz1*dz1 + 1e-12f);
            f1 = 0.5f * __cosf((CUDART_PI_F / RCA) * d1) + 0.5f;
            e1v = elem[m*NA + a1];
            in1 = (a1 != i) && (d1 < RCA);
        }
        const unsigned b0 = __ballot_sync(0xFFFFFFFFu, in0);
        const unsigned b1 = __ballot_sync(0xFFFFFFFFu, in1);
        const unsigned lt = (1u << lane) - 1u;
        if (in0) {
            int p = __popc(b0 & lt);
            adx[p]=dx0; ady[p]=dy0; adz[p]=dz0; ad[p]=d0; afc[p]=f0; ael[p]=e0;
        }
        if (in1) {
            int p = __popc(b0) + __popc(b1 & lt);
            adx[p]=dx1; ady[p]=dy1; adz[p]=dz1; ad[p]=d1; afc[p]=f1; ael[p]=e1v;
        }
        const int cntA = __popc(b0) + __popc(b1);
        const int np   = cntA * (cntA - 1) / 2;
        __syncwarp();

        // lane owns (a,t); this warp owns pids [aw*5, aw*5+5)
        const int a = lane >> 3;
        const int t = lane & 7;
        const float shfa = 0.9f + 0.65f * (float)a;
        const float z = (CUDART_PI_F / 16.0f) * (float)(2*t + 1);
        float sz, cz;
        __sincosf(z, &sz, &cz);
        const int pid0 = aw * 5;
        float acc[5];
        #pragma unroll
        for (int q = 0; q < 5; q++) acc[q] = 0.0f;

        // Rounds of 32 pairs: build (lane = one pair), then branchless scan
        for (int base = 0; base < np; base += 32) {
            const int n = min(32, np - base);
            if (lane < n) {
                const int q = base + lane;
                int jj = 0, rem = q, row = cntA - 1;
                while (rem >= row) { rem -= row; row--; jj++; }
                int kk = jj + 1 + rem;
                float dot = adx[jj]*adx[kk] + ady[jj]*ady[kk] + adz[jj]*adz[kk];
                float dj = ad[jj], dk = ad[kk];
                float c  = 0.95f * __fdividef(dot, dj * dk);   // |c| <= 0.95
                float sn = sqrtf(1.0f - c*c);                  // sin(acos(c)) >= 0
                pd[lane] = make_float4(c, sn, 0.5f*(dj + dk), afc[jj]*afc[kk]);
                int ej = ael[jj], ek = ael[kk];
                int lo = min(ej, ek), hi = max(ej, ek);
                pidb[lane] = lo*NSPEC - (lo*(lo-1))/2 + (hi - lo);
            }
            __syncwarp();
            for (int p = 0; p < n; p++) {
                const int    pid = pidb[p];   // warp-uniform broadcast
                const float4 r   = pd[p];     // broadcast LDS.128
                float cth = r.x*cz + r.y*sz;  // cos(theta - z)
                float x   = 0.5f + 0.5f*cth;
                float x2  = x*x;
                float x4  = x2*x2;
                float x8  = x4*x4;
                float x16 = x8*x8;
                float x32 = x16*x16;          // x^ZETA, ZETA=32
                float dr  = r.z - shfa;
                float term = 2.0f * __expf(-8.0f * dr * dr) * x32 * r.w;
                #pragma unroll
                for (int q = 0; q < 5; q++)
                    acc[q] += (pid == pid0 + q) ? term : 0.0f;   // select-add
            }
            __syncwarp();
        }

        // Store this warp's 5 pid rows (coalesced 128B per row)
        #pragma unroll
        for (int q = 0; q < 5; q++)
            o[64 + (pid0 + q)*32 + lane] = acc[q];
    }
}

extern "C" void kernel_launch(void* const* d_in, const int* in_sizes, int n_in,
                              void* d_out, int out_size)
{
    const int*   elem   = (const int*)  d_in[0];   // elem_idxs (M*A) int32
    const float* coords = (const float*)d_in[1];   // coords (M*A*3) float32
    float*       out    = (float*)d_out;           // (M*A*FEAT) float32
    (void)in_sizes; (void)n_in; (void)out_size;
    aev_kernel<<<NM * NA, BLK>>>(elem, coords, out);
}

// round 9
// speedup vs baseline: 1.0142x; 1.0142x over previous
#include <cuda_runtime.h>
#include <math_constants.h>

// Problem constants (fixed by the reference)
#define NM   32      // molecules
#define NA   40      // atoms per molecule
#define NSPEC 4
#define FEAT 384     // 4*16 + 10*32
#define RCR  5.2f
#define RCA  3.5f
#define BLK  128

__global__ __launch_bounds__(BLK)
void aev_kernel(const int* __restrict__ elem,
                const float* __restrict__ coords,
                float* __restrict__ out)
{
    const int bid  = blockIdx.x;        // m*NA + i
    const int m    = bid / NA;
    const int i    = bid % NA;
    const int tid  = threadIdx.x;
    const int lane = tid & 31;
    const int w    = tid >> 5;

    // Warp-private compacted angular geometry (each warp builds its own copy)
    __shared__ float  s_adx[4][NA], s_ady[4][NA], s_adz[4][NA];
    __shared__ float  s_ad[4][NA],  s_afc[4][NA];
    __shared__ int    s_ael[4][NA];
    // Warp-private radial data (warps 0,1 only)
    __shared__ float2 s_rdat[2][NA];
    __shared__ int    s_rel[2][NA];
    // Warp-private pair records (per 32-pair round)
    __shared__ float4 s_pd[4][32];
    __shared__ int    s_pidb[4][32];
    // Angular partials: [warp][pid][lane] (lane stride-1 -> conflict-free reads)
    __shared__ float  s_part[4][10][32];

    const float xi = coords[(m*NA + i)*3 + 0];
    const float yi = coords[(m*NA + i)*3 + 1];
    const float zi = coords[(m*NA + i)*3 + 2];
    float* o = out + bid * FEAT;

    // ---- Geometry (every warp, redundant; no cross-warp sync needed) ----
    float* adx = s_adx[w]; float* ady = s_ady[w]; float* adz = s_adz[w];
    float* ad  = s_ad[w];  float* afc = s_afc[w]; int*   ael = s_ael[w];

    bool inR0=false, inA0=false, inR1=false, inA1=false;
    float dx0=0,dy0=0,dz0=0,d0=0,fA0=0,fR0=0;
    float dx1=0,dy1=0,dz1=0,d1=0,fA1=0,fR1=0;
    int   e0=0, e1v=0;
    {   // atom a0 = lane
        const float* cj = coords + (m*NA + lane)*3;
        dx0 = cj[0]-xi; dy0 = cj[1]-yi; dz0 = cj[2]-zi;
        d0  = sqrtf(dx0*dx0 + dy0*dy0 + dz0*dz0 + 1e-12f);
        fR0 = 0.5f * __cosf((CUDART_PI_F / RCR) * d0) + 0.5f;
        fA0 = 0.5f * __cosf((CUDART_PI_F / RCA) * d0) + 0.5f;
        e0  = elem[m*NA + lane];
        inR0 = (lane != i) && (d0 < RCR);
        inA0 = (lane != i) && (d0 < RCA);
    }
    if (lane < 8) {   // atom a1 = lane+32
        const int a1 = lane + 32;
        const float* cj = coords + (m*NA + a1)*3;
        dx1 = cj[0]-xi; dy1 = cj[1]-yi; dz1 = cj[2]-zi;
        d1  = sqrtf(dx1*dx1 + dy1*dy1 + dz1*dz1 + 1e-12f);
        fR1 = 0.5f * __cosf((CUDART_PI_F / RCR) * d1) + 0.5f;
        fA1 = 0.5f * __cosf((CUDART_PI_F / RCA) * d1) + 0.5f;
        e1v = elem[m*NA + a1];
        inR1 = (a1 != i) && (d1 < RCR);
        inA1 = (a1 != i) && (d1 < RCA);
    }
    const unsigned bR0 = __ballot_sync(0xFFFFFFFFu, inR0);
    const unsigned bA0 = __ballot_sync(0xFFFFFFFFu, inA0);
    const unsigned bR1 = __ballot_sync(0xFFFFFFFFu, inR1);
    const unsigned bA1 = __ballot_sync(0xFFFFFFFFu, inA1);
    const unsigned lt  = (1u << lane) - 1u;

    if (inA0) {
        int p = __popc(bA0 & lt);
        adx[p]=dx0; ady[p]=dy0; adz[p]=dz0; ad[p]=d0; afc[p]=fA0; ael[p]=e0;
    }
    if (inA1) {
        int p = __popc(bA0) + __popc(bA1 & lt);
        adx[p]=dx1; ady[p]=dy1; adz[p]=dz1; ad[p]=d1; afc[p]=fA1; ael[p]=e1v;
    }
    if (w < 2) {
        if (inR0) { int p = __popc(bR0 & lt);              s_rdat[w][p]=make_float2(d0,fR0); s_rel[w][p]=e0;  }
        if (inR1) { int p = __popc(bR0) + __popc(bR1 & lt); s_rdat[w][p]=make_float2(d1,fR1); s_rel[w][p]=e1v; }
    }
    const int cntR = __popc(bR0) + __popc(bR1);
    const int cntA = __popc(bA0) + __popc(bA1);
    const int np   = cntA * (cntA - 1) / 2;
    __syncwarp();

    // ---- Radial features (warps 0,1; 32 features each) ----
    if (w < 2) {
        const int f  = w*32 + lane;
        const int s  = f >> 4;
        const int fr = f & 15;
        const float shf = 0.9f + 0.26875f * (float)fr;
        float racc = 0.0f;
        #pragma unroll 4
        for (int n = 0; n < cntR; n++) {
            float2 rd = s_rdat[w][n];
            int    re = s_rel[w][n];
            float dd = rd.x - shf;
            float t  = 0.25f * __expf(-16.0f * dd * dd) * rd.y;
            racc += (re == s) ? t : 0.0f;
        }
        o[f] = racc;
    }

    // ---- Angular: warp w owns global pairs q = w, w+4, w+8, ... ----
    const int a = lane >> 3;
    const int t = lane & 7;
    const float shfa = 0.9f + 0.65f * (float)a;
    const float z = (CUDART_PI_F / 16.0f) * (float)(2*t + 1);
    float sz, cz;
    __sincosf(z, &sz, &cz);
    float acc[10];
    #pragma unroll
    for (int q = 0; q < 10; q++) acc[q] = 0.0f;

    const int nloc = (np > w) ? (np - w + 3) >> 2 : 0;   // ceil((np-w)/4)
    float4* pd   = s_pd[w];
    int*    pidb = s_pidb[w];

    for (int lbase = 0; lbase < nloc; lbase += 32) {
        const int n = min(32, nloc - lbase);
        if (lane < n) {
            const int q = w + 4*(lbase + lane);           // global pair index
            int jj = 0, rem = q, row = cntA - 1;
            while (rem >= row) { rem -= row; row--; jj++; }
            int kk = jj + 1 + rem;
            float dot = adx[jj]*adx[kk] + ady[jj]*ady[kk] + adz[jj]*adz[kk];
            float dj = ad[jj], dk = ad[kk];
            float c  = 0.95f * __fdividef(dot, dj * dk);  // |c| <= 0.95
            float sn = sqrtf(1.0f - c*c);                 // sin(acos(c)) >= 0
            pd[lane] = make_float4(c, sn, 0.5f*(dj + dk), afc[jj]*afc[kk]);
            int ej = ael[jj], ek = ael[kk];
            int lo = min(ej, ek), hi = max(ej, ek);
            pidb[lane] = lo*NSPEC - (lo*(lo-1))/2 + (hi - lo);
        }
        __syncwarp();
        for (int p = 0; p < n; p++) {
            const int    pid = pidb[p];   // warp-uniform broadcast
            const float4 r   = pd[p];     // broadcast LDS.128
            float cth = r.x*cz + r.y*sz;  // cos(theta - z)
            float x   = 0.5f + 0.5f*cth;
            float x2  = x*x;
            float x4  = x2*x2;
            float x8  = x4*x4;
            float x16 = x8*x8;
            float x32 = x16*x16;          // x^ZETA, ZETA=32
            float dr  = r.z - shfa;
            float term = 2.0f * __expf(-8.0f * dr * dr) * x32 * r.w;
            #pragma unroll
            for (int q = 0; q < 10; q++)
                acc[q] += (pid == q) ? term : 0.0f;       // select-add, no branch
        }
        __syncwarp();
    }

    // ---- Write partials, one BALANCED barrier, combine + store ----
    #pragma unroll
    for (int q = 0; q < 10; q++) s_part[w][q][lane] = acc[q];
    __syncthreads();

    // warp w reduces pids {w, w+4, w+8<10}
    #pragma unroll
    for (int q = w; q < 10; q += 4) {
        float v = s_part[0][q][lane] + s_part[1][q][lane]
                + s_part[2][q][lane] + s_part[3][q][lane];
        o[64 + q*32 + lane] = v;
    }
}

extern "C" void kernel_launch(void* const* d_in, const int* in_sizes, int n_in,
                              void* d_out, int out_size)
{
    const int*   elem   = (const int*)  d_in[0];   // elem_idxs (M*A) int32
    const float* coords = (const float*)d_in[1];   // coords (M*A*3) float32
    float*       out    = (float*)d_out;           // (M*A*FEAT) float32
    (void)in_sizes; (void)n_in; (void)out_size;
    aev_kernel<<<NM * NA, BLK>>>(elem, coords, out);
}

// round 10
// speedup vs baseline: 1.0251x; 1.0108x over previous
#include <cuda_runtime.h>
#include <math_constants.h>

// Problem constants (fixed by the reference)
#define NM   32      // molecules
#define NA   40      // atoms per molecule
#define NSPEC 4
#define FEAT 384     // 4*16 + 10*32
#define RCR  5.2f
#define RCA  3.5f
#define BLK  128

__global__ __launch_bounds__(BLK)
void aev_kernel(const int* __restrict__ elem,
                const float* __restrict__ coords,
                float* __restrict__ out)
{
    const int bid  = blockIdx.x;        // m*NA + i
    const int m    = bid / NA;
    const int i    = bid % NA;
    const int tid  = threadIdx.x;
    const int lane = tid & 31;
    const int w    = tid >> 5;

    // SINGLE shared copy of compacted geometry (built by warp 0 only)
    __shared__ float  adx[NA], ady[NA], adz[NA], ad[NA], afc[NA];
    __shared__ int    ael[NA];
    __shared__ float2 rdat[NA];         // {d, fcR}
    __shared__ int    rel[NA];
    __shared__ int    scnt[2];          // cntR, cntA
    // Warp-private pair records (per 32-pair round)
    __shared__ float4 s_pd[4][32];
    __shared__ int    s_pidb[4][32];
    // Angular partials: [warp][pid][lane] (lane stride-1 -> conflict-free)
    __shared__ float  s_part[4][10][32];

    float* o = out + bid * FEAT;

    // ---- Angular per-lane setup (ALL warps, before the barrier: overlaps w0) ----
    const int at = lane >> 3;
    const int tt = lane & 7;
    const float shfa = 0.9f + 0.65f * (float)at;
    const float z = (CUDART_PI_F / 16.0f) * (float)(2*tt + 1);
    float sz, cz;
    __sincosf(z, &sz, &cz);

    // ---- Phase 1 (warp 0 only): geometry + ballots + compacted scatter ----
    if (w == 0) {
        const float xi = coords[(m*NA + i)*3 + 0];
        const float yi = coords[(m*NA + i)*3 + 1];
        const float zi = coords[(m*NA + i)*3 + 2];

        bool inR0=false, inA0=false, inR1=false, inA1=false;
        float dx0=0,dy0=0,dz0=0,d0=0,fA0=0,fR0=0;
        float dx1=0,dy1=0,dz1=0,d1=0,fA1=0,fR1=0;
        int   e0=0, e1v=0;
        {   // atom a0 = lane
            const float* cj = coords + (m*NA + lane)*3;
            dx0 = cj[0]-xi; dy0 = cj[1]-yi; dz0 = cj[2]-zi;
            d0  = sqrtf(dx0*dx0 + dy0*dy0 + dz0*dz0 + 1e-12f);
            fR0 = 0.5f * __cosf((CUDART_PI_F / RCR) * d0) + 0.5f;
            fA0 = 0.5f * __cosf((CUDART_PI_F / RCA) * d0) + 0.5f;
            e0  = elem[m*NA + lane];
            inR0 = (lane != i) && (d0 < RCR);
            inA0 = (lane != i) && (d0 < RCA);
        }
        if (lane < 8) {   // atom a1 = lane+32
            const int a1 = lane + 32;
            const float* cj = coords + (m*NA + a1)*3;
            dx1 = cj[0]-xi; dy1 = cj[1]-yi; dz1 = cj[2]-zi;
            d1  = sqrtf(dx1*dx1 + dy1*dy1 + dz1*dz1 + 1e-12f);
            fR1 = 0.5f * __cosf((CUDART_PI_F / RCR) * d1) + 0.5f;
            fA1 = 0.5f * __cosf((CUDART_PI_F / RCA) * d1) + 0.5f;
            e1v = elem[m*NA + a1];
            inR1 = (a1 != i) && (d1 < RCR);
            inA1 = (a1 != i) && (d1 < RCA);
        }
        const unsigned bR0 = __ballot_sync(0xFFFFFFFFu, inR0);
        const unsigned bA0 = __ballot_sync(0xFFFFFFFFu, inA0);
        const unsigned bR1 = __ballot_sync(0xFFFFFFFFu, inR1);
        const unsigned bA1 = __ballot_sync(0xFFFFFFFFu, inA1);
        const unsigned lt  = (1u << lane) - 1u;

        if (inA0) {
            int p = __popc(bA0 & lt);
            adx[p]=dx0; ady[p]=dy0; adz[p]=dz0; ad[p]=d0; afc[p]=fA0; ael[p]=e0;
        }
        if (inA1) {
            int p = __popc(bA0) + __popc(bA1 & lt);
            adx[p]=dx1; ady[p]=dy1; adz[p]=dz1; ad[p]=d1; afc[p]=fA1; ael[p]=e1v;
        }
        if (inR0) { int p = __popc(bR0 & lt);               rdat[p]=make_float2(d0,fR0); rel[p]=e0;  }
        if (inR1) { int p = __popc(bR0) + __popc(bR1 & lt); rdat[p]=make_float2(d1,fR1); rel[p]=e1v; }
        if (lane == 0) {
            scnt[0] = __popc(bR0) + __popc(bR1);
            scnt[1] = __popc(bA0) + __popc(bA1);
        }
    }
    __syncthreads();

    const int cntR = scnt[0];
    const int cntA = scnt[1];
    const int np   = cntA * (cntA - 1) / 2;

    // ---- Radial features (warps 0,1; 32 features each) ----
    if (w < 2) {
        const int f  = w*32 + lane;
        const int s  = f >> 4;
        const int fr = f & 15;
        const float shf = 0.9f + 0.26875f * (float)fr;
        float racc = 0.0f;
        #pragma unroll 4
        for (int n = 0; n < cntR; n++) {
            float2 rd = rdat[n];
            int    re = rel[n];
            float dd = rd.x - shf;
            float t  = 0.25f * __expf(-16.0f * dd * dd) * rd.y;
            racc += (re == s) ? t : 0.0f;
        }
        o[f] = racc;
    }

    // ---- Angular: warp w owns global pairs q = w, w+4, w+8, ... ----
    float acc[10];
    #pragma unroll
    for (int q = 0; q < 10; q++) acc[q] = 0.0f;

    const int nloc = (np > w) ? (np - w + 3) >> 2 : 0;   // ceil((np-w)/4)
    float4* pd   = s_pd[w];
    int*    pidb = s_pidb[w];

    for (int lbase = 0; lbase < nloc; lbase += 32) {
        const int n = min(32, nloc - lbase);
        if (lane < n) {
            const int q = w + 4*(lbase + lane);           // global pair index
            int jj = 0, rem = q, row = cntA - 1;
            while (rem >= row) { rem -= row; row--; jj++; }
            int kk = jj + 1 + rem;
            float dot = adx[jj]*adx[kk] + ady[jj]*ady[kk] + adz[jj]*adz[kk];
            float dj = ad[jj], dk = ad[kk];
            float c  = 0.95f * __fdividef(dot, dj * dk);  // |c| <= 0.95
            float sn = sqrtf(1.0f - c*c);                 // sin(acos(c)) >= 0
            pd[lane] = make_float4(c, sn, 0.5f*(dj + dk), afc[jj]*afc[kk]);
            int ej = ael[jj], ek = ael[kk];
            int lo = min(ej, ek), hi = max(ej, ek);
            pidb[lane] = lo*NSPEC - (lo*(lo-1))/2 + (hi - lo);
        }
        __syncwarp();
        for (int p = 0; p < n; p++) {
            const int    pid = pidb[p];   // warp-uniform broadcast
            const float4 r   = pd[p];     // broadcast LDS.128
            float cth = r.x*cz + r.y*sz;  // cos(theta - z)
            float x   = 0.5f + 0.5f*cth;
            float x2  = x*x;
            float x4  = x2*x2;
            float x8  = x4*x4;
            float x16 = x8*x8;
            float x32 = x16*x16;          // x^ZETA, ZETA=32
            float dr  = r.z - shfa;
            float term = 2.0f * __expf(-8.0f * dr * dr) * x32 * r.w;
            #pragma unroll
            for (int q = 0; q < 10; q++)
                acc[q] += (pid == q) ? term : 0.0f;       // select-add, no branch
        }
        __syncwarp();
    }

    // ---- Write partials, balanced barrier, combine + store ----
    #pragma unroll
    for (int q = 0; q < 10; q++) s_part[w][q][lane] = acc[q];
    __syncthreads();

    // warp w reduces pids {w, w+4, w+8<10}
    #pragma unroll
    for (int q = w; q < 10; q += 4) {
        float v = s_part[0][q][lane] + s_part[1][q][lane]
                + s_part[2][q][lane] + s_part[3][q][lane];
        o[64 + q*32 + lane] = v;
    }
}

extern "C" void kernel_launch(void* const* d_in, const int* in_sizes, int n_in,
                              void* d_out, int out_size)
{
    const int*   elem   = (const int*)  d_in[0];   // elem_idxs (M*A) int32
    const float* coords = (const float*)d_in[1];   // coords (M*A*3) float32
    float*       out    = (float*)d_out;           // (M*A*FEAT) float32
    (void)in_sizes; (void)n_in; (void)out_size;
    aev_kernel<<<NM * NA, BLK>>>(elem, coords, out);
}

// round 12
// speedup vs baseline: 1.1128x; 1.0856x over previous
#include <cuda_runtime.h>
#include <math_constants.h>

// Problem constants (fixed by the reference)
#define NM   32      // molecules
#define NA   40      // atoms per molecule
#define NSPEC 4
#define FEAT 384     // 4*16 + 10*32
#define RCR  5.2f
#define RCA  3.5f
#define BLK  128

__global__ __launch_bounds__(BLK)
void aev_kernel(const int* __restrict__ elem,
                const float* __restrict__ coords,
                float* __restrict__ out)
{
    const int bid  = blockIdx.x;        // m*NA + i
    const int m    = bid / NA;
    const int i    = bid % NA;
    const int tid  = threadIdx.x;
    const int lane = tid & 31;
    const int w    = tid >> 5;

    // Compacted angular geometry (vectorized), built by warp 0
    __shared__ float4 s_ag[NA];         // {dx, dy, dz, d}
    __shared__ float2 s_af[NA];         // {fcA, elem-as-float-bits}
    // Radial records grouped by species; srOff[s]..srOff[s+1] = species-s segment
    __shared__ float2 s_rd[NA];         // {d, fcR}
    __shared__ int    srOff[5];
    __shared__ int    scntA;
    // Warp-private pair records (per 32-pair round)
    __shared__ float4 s_pd[4][32];
    __shared__ int    s_pidb[4][32];
    // Angular partials: [warp][pid][lane] (lane stride-1 -> conflict-free)
    __shared__ float  s_part[4][10][32];

    float* o = out + bid * FEAT;

    // ---- Angular per-lane setup (ALL warps, overlaps warp-0 prologue) ----
    const int at = lane >> 3;
    const int tt = lane & 7;
    const float shfa = 0.9f + 0.65f * (float)at;
    const float z = (CUDART_PI_F / 16.0f) * (float)(2*tt + 1);
    float sz, cz;
    __sincosf(z, &sz, &cz);

    // ---- Phase 1 (warp 0 only): geometry + species-sorted compaction ----
    if (w == 0) {
        const float xi = coords[(m*NA + i)*3 + 0];
        const float yi = coords[(m*NA + i)*3 + 1];
        const float zi = coords[(m*NA + i)*3 + 2];

        bool inR0=false, inA0=false, inR1=false, inA1=false;
        float dx0=0,dy0=0,dz0=0,d0=0,fA0=0,fR0=0;
        float dx1=0,dy1=0,dz1=0,d1=0,fA1=0,fR1=0;
        int   e0=0, e1v=0;
        {   // atom a0 = lane
            const float* cj = coords + (m*NA + lane)*3;
            dx0 = cj[0]-xi; dy0 = cj[1]-yi; dz0 = cj[2]-zi;
            d0  = sqrtf(dx0*dx0 + dy0*dy0 + dz0*dz0 + 1e-12f);
            fR0 = 0.5f * __cosf((CUDART_PI_F / RCR) * d0) + 0.5f;
            fA0 = 0.5f * __cosf((CUDART_PI_F / RCA) * d0) + 0.5f;
            e0  = elem[m*NA + lane];
            inR0 = (lane != i) && (d0 < RCR);
            inA0 = (lane != i) && (d0 < RCA);
        }
        if (lane < 8) {   // atom a1 = lane+32
            const int a1 = lane + 32;
            const float* cj = coords + (m*NA + a1)*3;
            dx1 = cj[0]-xi; dy1 = cj[1]-yi; dz1 = cj[2]-zi;
            d1  = sqrtf(dx1*dx1 + dy1*dy1 + dz1*dz1 + 1e-12f);
            fR1 = 0.5f * __cosf((CUDART_PI_F / RCR) * d1) + 0.5f;
            fA1 = 0.5f * __cosf((CUDART_PI_F / RCA) * d1) + 0.5f;
            e1v = elem[m*NA + a1];
            inR1 = (a1 != i) && (d1 < RCR);
            inA1 = (a1 != i) && (d1 < RCA);
        }

        // Angular compaction (ascending order)
        const unsigned bA0 = __ballot_sync(0xFFFFFFFFu, inA0);
        const unsigned bA1 = __ballot_sync(0xFFFFFFFFu, inA1);
        const unsigned lt  = (1u << lane) - 1u;
        if (inA0) {
            int p = __popc(bA0 & lt);
            s_ag[p] = make_float4(dx0, dy0, dz0, d0);
            s_af[p] = make_float2(fA0, __int_as_float(e0));
        }
        if (inA1) {
            int p = __popc(bA0) + __popc(bA1 & lt);
            s_ag[p] = make_float4(dx1, dy1, dz1, d1);
            s_af[p] = make_float2(fA1, __int_as_float(e1v));
        }

        // Radial compaction GROUPED BY SPECIES (per-species ballots)
        unsigned bs0[NSPEC], bs1[NSPEC];
        #pragma unroll
        for (int s = 0; s < NSPEC; s++) {
            bs0[s] = __ballot_sync(0xFFFFFFFFu, inR0 && (e0  == s));
            bs1[s] = __ballot_sync(0xFFFFFFFFu, inR1 && (e1v == s));
        }
        int off[NSPEC + 1];
        off[0] = 0;
        #pragma unroll
        for (int s = 0; s < NSPEC; s++)
            off[s+1] = off[s] + __popc(bs0[s]) + __popc(bs1[s]);
        if (inR0) {
            int p = off[e0] + __popc(bs0[e0] & lt);
            s_rd[p] = make_float2(d0, fR0);
        }
        if (inR1) {
            int p = off[e1v] + __popc(bs0[e1v]) + __popc(bs1[e1v] & lt);
            s_rd[p] = make_float2(d1, fR1);
        }
        if (lane < 5) srOff[lane] = off[lane];
        if (lane == 0) scntA = __popc(bA0) + __popc(bA1);
    }
    __syncthreads();

    const int cntA = scntA;
    const int np   = cntA * (cntA - 1) / 2;

    // ---- Radial features (warps 0,1): species-s segment only (~3 iters) ----
    if (w < 2) {
        const int f  = w*32 + lane;
        const int s  = f >> 4;
        const int fr = f & 15;
        const float shf = 0.9f + 0.26875f * (float)fr;
        const int n0 = srOff[s], n1 = srOff[s+1];
        float racc = 0.0f;
        #pragma unroll 2
        for (int n = n0; n < n1; n++) {
            float2 rd = s_rd[n];
            float dd = rd.x - shf;
            racc += 0.25f * __expf(-16.0f * dd * dd) * rd.y;
        }
        o[f] = racc;
    }

    // ---- Angular: warp w owns global pairs q = w, w+4, w+8, ... ----
    float acc[10];
    #pragma unroll
    for (int q = 0; q < 10; q++) acc[q] = 0.0f;

    const int nloc = (np > w) ? (np - w + 3) >> 2 : 0;   // ceil((np-w)/4)
    float4* pd   = s_pd[w];
    int*    pidb = s_pidb[w];

    for (int lbase = 0; lbase < nloc; lbase += 32) {
        const int n = min(32, nloc - lbase);
        if (lane < n) {
            const int q = w + 4*(lbase + lane);           // global pair index
            int jj = 0, rem = q, row = cntA - 1;
            while (rem >= row) { rem -= row; row--; jj++; }
            int kk = jj + 1 + rem;
            const float4 gj = s_ag[jj], gk = s_ag[kk];
            const float2 fj = s_af[jj], fk = s_af[kk];
            float dot = gj.x*gk.x + gj.y*gk.y + gj.z*gk.z;
            float dj = gj.w, dk = gk.w;
            float c  = 0.95f * __fdividef(dot, dj * dk);  // |c| <= 0.95
            float sn = sqrtf(1.0f - c*c);                 // sin(acos(c)) >= 0
            pd[lane] = make_float4(c, sn, 0.5f*(dj + dk), fj.x*fk.x);
            int ej = __float_as_int(fj.y), ek = __float_as_int(fk.y);
            int lo = min(ej, ek), hi = max(ej, ek);
            pidb[lane] = lo*NSPEC - (lo*(lo-1))/2 + (hi - lo);
        }
        __syncwarp();
        #pragma unroll 4
        for (int p = 0; p < n; p++) {
            const int    pid = pidb[p];   // warp-uniform broadcast
            const float4 r   = pd[p];     // broadcast LDS.128
            float cth = r.x*cz + r.y*sz;  // cos(theta - z)
            float x   = 0.5f + 0.5f*cth;
            float x2  = x*x;
            float x4  = x2*x2;
            float x8  = x4*x4;
            float x16 = x8*x8;
            float x32 = x16*x16;          // x^ZETA, ZETA=32
            float dr  = r.z - shfa;
            float term = 2.0f * __expf(-8.0f * dr * dr) * x32 * r.w;
            #pragma unroll
            for (int q = 0; q < 10; q++)
                acc[q] += (pid == q) ? term : 0.0f;       // select-add, no branch
        }
        __syncwarp();
    }

    // ---- Write partials, balanced barrier, combine + store ----
    #pragma unroll
    for (int q = 0; q < 10; q++) s_part[w][q][lane] = acc[q];
    __syncthreads();

    // warp w reduces pids {w, w+4, w+8<10}
    #pragma unroll
    for (int q = w; q < 10; q += 4) {
        float v = s_part[0][q][lane] + s_part[1][q][lane]
                + s_part[2][q][lane] + s_part[3][q][lane];
        o[64 + q*32 + lane] = v;
    }
}

extern "C" void kernel_launch(void* const* d_in, const int* in_sizes, int n_in,
                              void* d_out, int out_size)
{
    const int*   elem   = (const int*)  d_in[0];   // elem_idxs (M*A) int32
    const float* coords = (const float*)d_in[1];   // coords (M*A*3) float32
    float*       out    = (float*)d_out;           // (M*A*FEAT) float32
    (void)in_sizes; (void)n_in; (void)out_size;
    aev_kernel<<<NM * NA, BLK>>>(elem, coords, out);
}